// round 5
// baseline (speedup 1.0000x reference)
#include <cuda_runtime.h>
#include <cuda_bf16.h>

#define Cc    9
#define KSc   9
#define OUTc  16
#define NBc   16
#define Vc    20000
#define Bc    2
#define CPAD  12        // padded row: 3 x float4
#define KH    5         // k-slots per lane: k = 2j + p, j<5 (p=1,j=4 masked)

// padded, 16B-aligned copy of x  (2*20000*3 float4 = 1.92 MB)
__device__ float4 xpad4[Bc * Vc * (CPAD / 4)];

__global__ __launch_bounds__(256)
void pad_kernel(const float* __restrict__ x)
{
    int r = blockIdx.x * blockDim.x + threadIdx.x;   // row over B*V
    if (r >= Bc * Vc) return;
    const float* src = x + (size_t)r * Cc;
    float4 v0 = make_float4(src[0], src[1], src[2], src[3]);
    float4 v1 = make_float4(src[4], src[5], src[6], src[7]);
    float4 v2 = make_float4(src[8], 0.0f, 0.0f, 0.0f);
    float4* dst = xpad4 + (size_t)r * 3;
    dst[0] = v0; dst[1] = v1; dst[2] = v2;
}

__global__ __launch_bounds__(128, 4)
void nlayer_kernel(const float* __restrict__ W,
                   const int*   __restrict__ adj,
                   float*       __restrict__ out)
{
    __shared__ float Wsh[Cc * KSc * OUTc];   // 1296 floats
    for (int i = threadIdx.x; i < Cc * KSc * OUTc; i += blockDim.x)
        Wsh[i] = W[i];
    __syncthreads();

    int tid   = blockIdx.x * blockDim.x + threadIdx.x;
    int group = tid >> 2;          // vertex index over B*V
    int l     = tid & 3;
    int p     = l & 1;             // k-half:      k = 2j + p
    int q     = l >> 1;            // neighbor half + o-half
    if (group >= Bc * Vc) return;  // never taken (160000 % 128 == 0)

    int b = group / Vc;
    int v = group - b * Vc;
    const float4* xb4 = xpad4 + (size_t)b * Vc * 3;

    // center vertex features (all 4 lanes same addresses -> merged)
    float xv[Cc];
    {
        float4 v0 = __ldg(&xb4[(size_t)v * 3 + 0]);
        float4 v1 = __ldg(&xb4[(size_t)v * 3 + 1]);
        float4 v2 = __ldg(&xb4[(size_t)v * 3 + 2]);
        xv[0]=v0.x; xv[1]=v0.y; xv[2]=v0.z; xv[3]=v0.w;
        xv[4]=v1.x; xv[5]=v1.y; xv[6]=v1.z; xv[7]=v1.w;
        xv[8]=v2.x;
    }

    // this lane's neighbor half: neighbors [8q, 8q+8) -> two int4
    const int4* adj4 = reinterpret_cast<const int4*>(adj + (size_t)v * NBc);
    int4 a0 = __ldg(&adj4[2 * q + 0]);
    int4 a1 = __ldg(&adj4[2 * q + 1]);
    int a[8] = {a0.x, a0.y, a0.z, a0.w, a1.x, a1.y, a1.z, a1.w};

    // partial s for this lane's k-slots over its neighbor half
    float s[KH][Cc];
    #pragma unroll
    for (int j = 0; j < KH; j++)
        #pragma unroll
        for (int c = 0; c < Cc; c++) s[j][c] = 0.0f;

    int deg = 0;

    #pragma unroll
    for (int n = 0; n < 8; n++) {
        int an    = a[n];
        int valid = (an != 0);
        deg += valid;
        int ridx = valid ? (an - 1) : 0;

        const float4* nr = xb4 + (size_t)ridx * 3;
        float4 n0 = __ldg(&nr[0]);
        float4 n1 = __ldg(&nr[1]);
        float4 n2 = __ldg(&nr[2]);
        float nbv[Cc] = {n0.x, n0.y, n0.z, n0.w, n1.x, n1.y, n1.z, n1.w, n2.x};

        float d[Cc];
        #pragma unroll
        for (int c = 0; c < Cc; c++) d[c] = xv[c] - nbv[c];

        float m = d[0];
        #pragma unroll
        for (int c = 1; c < Cc; c++) m = fmaxf(m, d[c]);
        float e[Cc], sum = 0.0f;
        #pragma unroll
        for (int c = 0; c < Cc; c++) { e[c] = __expf(d[c] - m); sum += e[c]; }
        float inv = __fdividef(1.0f, sum);
        float msk = valid ? inv : 0.0f;

        // q-factors for this lane's k-slots: k = 2j + p
        #pragma unroll
        for (int j = 0; j < KH; j++) {
            int k = 2 * j + p;
            float qk = (k < KSc) ? e[k] * msk : 0.0f;
            #pragma unroll
            for (int c = 0; c < Cc; c++)
                s[j][c] = fmaf(qk, nbv[c], s[j][c]);
        }
    }

    // reduce s and deg across the two neighbor halves (xor 2)
    deg += __shfl_xor_sync(0xffffffffu, deg, 2);
    #pragma unroll
    for (int j = 0; j < KH; j++)
        #pragma unroll
        for (int c = 0; c < Cc; c++)
            s[j][c] += __shfl_xor_sync(0xffffffffu, s[j][c], 2);

    float invdeg = (deg > 0) ? (1.0f / (float)deg) : 0.0f;

    // lane contracts its k-slice into its o-half [8q, 8q+8)
    float acc[8];
    #pragma unroll
    for (int o = 0; o < 8; o++) acc[o] = 0.0f;

    #pragma unroll
    for (int c = 0; c < Cc; c++) {
        #pragma unroll
        for (int j = 0; j < KH; j++) {
            int k = 2 * j + p;
            if (k > 8) k = 8;            // s[4][*]==0 for p==1; value irrelevant
            float sc = s[j][c];
            const float* wrow = &Wsh[(c * KSc + k) * OUTc + 8 * q];
            float4 w0 = *reinterpret_cast<const float4*>(wrow);
            float4 w1 = *reinterpret_cast<const float4*>(wrow + 4);
            acc[0] = fmaf(sc, w0.x, acc[0]);
            acc[1] = fmaf(sc, w0.y, acc[1]);
            acc[2] = fmaf(sc, w0.z, acc[2]);
            acc[3] = fmaf(sc, w0.w, acc[3]);
            acc[4] = fmaf(sc, w1.x, acc[4]);
            acc[5] = fmaf(sc, w1.y, acc[5]);
            acc[6] = fmaf(sc, w1.z, acc[6]);
            acc[7] = fmaf(sc, w1.w, acc[7]);
        }
    }

    // combine the two k-halves (xor 1); both p-lanes of a q now hold full acc
    #pragma unroll
    for (int o = 0; o < 8; o++)
        acc[o] += __shfl_xor_sync(0xffffffffu, acc[o], 1);

    // lane l stores o in [4l, 4l+4): l*4 = 8q + 4p  -> coalesced 64B per group
    float4 r;
    int ob = 4 * p;
    r.x = fmaxf(acc[ob + 0] * invdeg, 0.0f);
    r.y = fmaxf(acc[ob + 1] * invdeg, 0.0f);
    r.z = fmaxf(acc[ob + 2] * invdeg, 0.0f);
    r.w = fmaxf(acc[ob + 3] * invdeg, 0.0f);

    *reinterpret_cast<float4*>(out + (size_t)group * OUTc + 4 * l) = r;
}

extern "C" void kernel_launch(void* const* d_in, const int* in_sizes, int n_in,
                              void* d_out, int out_size)
{
    const float* x   = (const float*)d_in[0];   // (2, 20000, 9)
    const float* W   = (const float*)d_in[1];   // (9, 9, 16)
    const int*   adj = (const int*)d_in[2];     // (20000, 16)
    float*       out = (float*)d_out;           // (2, 20000, 16)

    // 1) pad x into 16B-aligned rows
    {
        const int total   = Bc * Vc;            // 40000
        const int threads = 256;
        pad_kernel<<<(total + threads - 1) / threads, threads>>>(x);
    }
    // 2) main kernel: 4 lanes per vertex
    {
        const int total   = Bc * Vc * 4;        // 160000
        const int threads = 128;
        nlayer_kernel<<<(total + threads - 1) / threads, threads>>>(W, adj, out);
    }
}